// round 1
// baseline (speedup 1.0000x reference)
#include <cuda_runtime.h>

// LFQ: z [4,14,32,32] f32, codebook [16384,14] (unused: it is exactly the +-1 bit
// pattern set, so the softmax factorizes per bit), codebook_used [65536] i32.
// Output layout (f32): quantized[57344], commit_loss, entropy_aux_loss,
// codebook_usage, idx_flat[4096]  -> 61443 elements.

#define N_TOK 4096
#define DIM   14
#define HW    1024
#define NE    16384
#define QELEMS (N_TOK * DIM)   // 57344

// scratch (device globals: no allocation allowed)
__device__ float        g_L[N_TOK * 128];       // low-7-bit products per token
__device__ float        g_Hh[N_TOK * 128];      // high-7-bit products per token
__device__ float        g_partial[64 * NE];     // per-token-group partial avg_probs sums
__device__ float        g_tok_commit[N_TOK];
__device__ float        g_tok_ent[N_TOK];
__device__ float        g_avg_ent_partial[64];
__device__ unsigned int g_bitset[2048];         // 65536-value presence bitset

// ---------------------------------------------------------------------------
__global__ void k_zero() {
    int i = blockIdx.x * blockDim.x + threadIdx.x;
    if (i < 2048) g_bitset[i] = 0u;
}

// mark ring-buffer leftovers codebook_used[4096:65536)
__global__ void k_mark_used(const int* __restrict__ used) {
    int i = blockIdx.x * blockDim.x + threadIdx.x;
    int stride = gridDim.x * blockDim.x;
    for (; i < 65536 - N_TOK; i += stride) {
        unsigned v = ((unsigned)used[N_TOK + i]) & 65535u;
        atomicOr(&g_bitset[v >> 5], 1u << (v & 31u));
    }
}

// ---------------------------------------------------------------------------
// One block (128 thr) per token: quantized, commit partial, idx, per-bit
// sigmoids -> L/H product tables, sample-entropy partial.
__global__ void k_token(const float* __restrict__ z, float* __restrict__ out) {
    int t  = blockIdx.x;
    int b  = t >> 10;
    int hw = t & 1023;
    int base = b * (DIM * HW) + hw;
    int tid = threadIdx.x;

    __shared__ float s_p1[DIM];
    __shared__ float s_p0[DIM];

    float ent = 0.f, com = 0.f;
    unsigned bit = 0u;

    if (tid < DIM) {
        float zv = z[base + tid * HW];
        float q  = (zv > 0.f) ? 1.f : -1.f;
        out[base + tid * HW] = q;                  // straight-through forward
        float df = zv - q;
        com = df * df;
        bit = (zv > 0.f) ? 1u : 0u;

        float x = 400.f * zv;                      // scaled per-bit logit delta
        s_p1[tid] = 1.f / (1.f + expf(-x));        // P(bit=1)
        s_p0[tid] = 1.f / (1.f + expf(x));         // P(bit=0)

        // binary entropy H(sigmoid(|x|)) = softplus(-|x|) + pmin*|x|
        float ax = fabsf(x);
        float em = expf(-ax);
        float sp = log1pf(em);
        float pmin = em / (1.f + em);
        ent = sp + pmin * ax;
    }

    if (tid < 32) {  // warp 0: idx via ballot + small reductions
        unsigned m = __ballot_sync(0xffffffffu, bit != 0u);
        #pragma unroll
        for (int o = 16; o; o >>= 1) {
            com += __shfl_down_sync(0xffffffffu, com, o);
            ent += __shfl_down_sync(0xffffffffu, ent, o);
        }
        if (tid == 0) {
            unsigned idx = m & 0x3FFFu;
            g_tok_commit[t] = com;
            g_tok_ent[t]    = ent;
            out[QELEMS + 3 + t] = (float)idx;      // idx_flat section
            atomicOr(&g_bitset[idx >> 5], 1u << (idx & 31u));
        }
    }
    __syncthreads();

    // each thread i in [0,128): product over 7 bits for low and high halves
    float Lv = 1.f, Hv = 1.f;
    #pragma unroll
    for (int d = 0; d < 7; d++) {
        Lv *= ((tid >> d) & 1) ? s_p1[d]     : s_p0[d];
        Hv *= ((tid >> d) & 1) ? s_p1[d + 7] : s_p0[d + 7];
    }
    g_L[t * 128 + tid]  = Lv;
    g_Hh[t * 128 + tid] = Hv;
}

// ---------------------------------------------------------------------------
// avg_probs accumulation. Block = (token group gid of 64 tokens, code half).
// Deterministic: fixed token order per block, disjoint output ranges.
__global__ void k_avg() {
    int gid  = blockIdx.x >> 1;
    int half = blockIdx.x & 1;
    int tid  = threadIdx.x;            // 256 threads

    __shared__ float acc[8192];
    __shared__ float sL[128];
    __shared__ float sH[64];

    for (int j = tid; j < 8192; j += 256) acc[j] = 0.f;
    __syncthreads();

    for (int tk = 0; tk < 64; tk++) {
        int t = gid * 64 + tk;
        if (tid < 128)      sL[tid] = g_L[t * 128 + tid];
        else if (tid < 192) sH[tid - 128] = g_Hh[t * 128 + half * 64 + (tid - 128)];
        __syncthreads();
        for (int j = tid; j < 8192; j += 256) {
            float v = sH[j >> 7] * sL[j & 127];
            if (v != 0.f) acc[j] += v;     // most products underflow to exactly 0
        }
        __syncthreads();
    }

    float* dst = &g_partial[gid * NE + half * 8192];
    for (int j = tid; j < 8192; j += 256) dst[j] = acc[j];
}

// ---------------------------------------------------------------------------
// Per-code reduce over 64 partials + avg-entropy term, block partial sums.
__global__ void k_reduce() {
    int j = blockIdx.x * 256 + threadIdx.x;   // 64 blocks x 256 = 16384 codes
    float s = 0.f;
    #pragma unroll 8
    for (int g = 0; g < 64; g++) s += g_partial[g * NE + j];
    float avg  = s * (1.f / 4096.f);
    float term = -avg * logf(avg + 1e-5f);    // avg==0 -> 0

    __shared__ float red[256];
    red[threadIdx.x] = term;
    __syncthreads();
    for (int o = 128; o; o >>= 1) {
        if (threadIdx.x < o) red[threadIdx.x] += red[threadIdx.x + o];
        __syncthreads();
    }
    if (threadIdx.x == 0) g_avg_ent_partial[blockIdx.x] = red[0];
}

// ---------------------------------------------------------------------------
__global__ void k_final(float* __restrict__ out) {
    __shared__ float redc[1024];
    __shared__ float rede[1024];
    __shared__ float reda[1024];
    __shared__ int   redn[1024];
    int tid = threadIdx.x;

    float cs = 0.f, es = 0.f, ae = 0.f;
    int cnt = 0;
    for (int i = tid; i < N_TOK; i += 1024) { cs += g_tok_commit[i]; es += g_tok_ent[i]; }
    if (tid < 64) ae = g_avg_ent_partial[tid];
    for (int i = tid; i < 2048; i += 1024) cnt += __popc(g_bitset[i]);

    redc[tid] = cs; rede[tid] = es; reda[tid] = ae; redn[tid] = cnt;
    __syncthreads();
    for (int o = 512; o; o >>= 1) {
        if (tid < o) {
            redc[tid] += redc[tid + o];
            rede[tid] += rede[tid + o];
            reda[tid] += reda[tid + o];
            redn[tid] += redn[tid + o];
        }
        __syncthreads();
    }
    if (tid == 0) {
        float commit   = 0.25f * redc[0] / (float)QELEMS;
        float sample_e = rede[0] / (float)N_TOK;
        float avg_e    = reda[0];
        float loss     = 0.1f * (sample_e - avg_e);
        float usage    = (float)redn[0] / (float)NE;
        out[QELEMS + 0] = commit;
        out[QELEMS + 1] = loss;
        out[QELEMS + 2] = usage;
    }
}

// ---------------------------------------------------------------------------
extern "C" void kernel_launch(void* const* d_in, const int* in_sizes, int n_in,
                              void* d_out, int out_size) {
    const float* z    = (const float*)d_in[0];
    const int*   used = (const int*)d_in[2];
    float*       out  = (float*)d_out;

    k_zero<<<8, 256>>>();
    k_mark_used<<<60, 256>>>(used);
    k_token<<<N_TOK, 128>>>(z, out);
    k_avg<<<128, 256>>>();
    k_reduce<<<64, 256>>>();
    k_final<<<1, 1024>>>(out);
}

// round 2
// speedup vs baseline: 2.4064x; 2.4064x over previous
#include <cuda_runtime.h>

// LFQ: z [4,14,32,32] f32. Codebook is exactly the +-1 bit-pattern set, so the
// T=0.01 softmax factorizes into per-bit sigmoids; in fp32 the "wrong bit"
// probability underflows to 0 for |z| >~ 0.26, so per token only a handful of
// the 16384 codes have nonzero probability -> sparse scatter into a u64
// fixed-point histogram (deterministic: integer atomics commute exactly).
//
// Output layout (f32): quantized[57344], commit_loss, entropy_aux_loss,
// codebook_usage, idx_flat[4096].

#define N_TOK 4096
#define DIM   14
#define HW    1024
#define NE    16384
#define QELEMS (N_TOK * DIM)   // 57344
#define FIXSCALE 1099511627776.0   // 2^40

__device__ unsigned long long g_hist[NE];   // fixed-point sum of probs per code
__device__ float              g_tok_commit[N_TOK];
__device__ float              g_tok_ent[N_TOK];
__device__ unsigned int       g_bitset[2048];

// ---------------------------------------------------------------------------
// Zero hist + bitset, mark ring-buffer leftovers used[4096:65536).
__global__ void k_init(const int* __restrict__ used) {
    int i = blockIdx.x * blockDim.x + threadIdx.x;   // 64 x 256 = 16384
    g_hist[i] = 0ull;
    if (i < 2048) g_bitset[i] = 0u;
    // 61440 leftovers: ~3.75 per thread
    for (int k = i; k < 65536 - N_TOK; k += 16384) {
        unsigned v = ((unsigned)used[N_TOK + k]) & 65535u;
        atomicOr(&g_bitset[v >> 5], 1u << (v & 31u));
    }
}

// ---------------------------------------------------------------------------
// One block (128 thr) per token.
__global__ void k_token(const float* __restrict__ z, float* __restrict__ out) {
    int t  = blockIdx.x;
    int b  = t >> 10;
    int hw = t & 1023;
    int base = b * (DIM * HW) + hw;
    int tid = threadIdx.x;

    __shared__ float s_p1[DIM];
    __shared__ float s_p0[DIM];
    __shared__ float sLval[128], sHval[128];
    __shared__ int   sLidx[128], sHidx[128];
    __shared__ int   s_cnt[2];   // [nnzL, nnzH]

    if (tid < 2) s_cnt[tid] = 0;

    float ent = 0.f, com = 0.f;
    unsigned bit = 0u;

    if (tid < DIM) {
        float zv = z[base + tid * HW];
        float q  = (zv > 0.f) ? 1.f : -1.f;
        out[base + tid * HW] = q;
        float df = zv - q;
        com = df * df;
        bit = (zv > 0.f) ? 1u : 0u;

        float x = 400.f * zv;
        s_p1[tid] = 1.f / (1.f + expf(-x));
        s_p0[tid] = 1.f / (1.f + expf(x));

        float ax = fabsf(x);
        float em = expf(-ax);
        float sp = log1pf(em);
        float pmin = em / (1.f + em);
        ent = sp + pmin * ax;
    }

    if (tid < 32) {
        unsigned m = __ballot_sync(0xffffffffu, bit != 0u);
        #pragma unroll
        for (int o = 16; o; o >>= 1) {
            com += __shfl_down_sync(0xffffffffu, com, o);
            ent += __shfl_down_sync(0xffffffffu, ent, o);
        }
        if (tid == 0) {
            unsigned idx = m & 0x3FFFu;
            g_tok_commit[t] = com;
            g_tok_ent[t]    = ent;
            out[QELEMS + 3 + t] = (float)idx;
            atomicOr(&g_bitset[idx >> 5], 1u << (idx & 31u));
        }
    }
    __syncthreads();

    // per-thread products over the 7 low / 7 high bits
    float Lv = 1.f, Hv = 1.f;
    #pragma unroll
    for (int d = 0; d < 7; d++) {
        Lv *= ((tid >> d) & 1) ? s_p1[d]     : s_p0[d];
        Hv *= ((tid >> d) & 1) ? s_p1[d + 7] : s_p0[d + 7];
    }

    // compact nonzeros (order irrelevant: downstream is integer atomics)
    if (Lv != 0.f) { int p = atomicAdd(&s_cnt[0], 1); sLval[p] = Lv; sLidx[p] = tid; }
    if (Hv != 0.f) { int p = atomicAdd(&s_cnt[1], 1); sHval[p] = Hv; sHidx[p] = tid; }
    __syncthreads();

    int nnzL = s_cnt[0], nnzH = s_cnt[1];
    int total = nnzL * nnzH;
    for (int k = tid; k < total; k += 128) {
        int i = k % nnzL;
        int j = k / nnzL;
        double p = (double)sLval[i] * (double)sHval[j];
        unsigned long long f = __double2ull_rn(p * FIXSCALE);
        if (f) atomicAdd(&g_hist[(sHidx[j] << 7) | sLidx[i]], f);
    }
}

// ---------------------------------------------------------------------------
// One block: histogram -> avg-entropy, token reductions, bitset popcount.
__global__ void k_finish(float* __restrict__ out) {
    __shared__ float redc[1024];
    __shared__ float rede[1024];
    __shared__ float reda[1024];
    __shared__ int   redn[1024];
    int tid = threadIdx.x;

    float ae = 0.f;
    #pragma unroll
    for (int k = 0; k < 16; k++) {
        int j = tid * 16 + k;            // fixed per-thread order: deterministic
        unsigned long long hv = g_hist[j];
        if (hv) {
            float avg = (float)((double)hv * (1.0 / FIXSCALE) * (1.0 / 4096.0));
            ae += -avg * logf(avg + 1e-5f);
        }
    }

    float cs = 0.f, es = 0.f;
    #pragma unroll
    for (int k = 0; k < 4; k++) {
        int i = tid * 4 + k;
        cs += g_tok_commit[i];
        es += g_tok_ent[i];
    }

    int cnt = __popc(g_bitset[tid]) + __popc(g_bitset[tid + 1024]);

    redc[tid] = cs; rede[tid] = es; reda[tid] = ae; redn[tid] = cnt;
    __syncthreads();
    for (int o = 512; o; o >>= 1) {
        if (tid < o) {
            redc[tid] += redc[tid + o];
            rede[tid] += rede[tid + o];
            reda[tid] += reda[tid + o];
            redn[tid] += redn[tid + o];
        }
        __syncthreads();
    }
    if (tid == 0) {
        float commit   = 0.25f * redc[0] / (float)QELEMS;
        float sample_e = rede[0] / (float)N_TOK;
        float loss     = 0.1f * (sample_e - reda[0]);
        float usage    = (float)redn[0] / (float)NE;
        out[QELEMS + 0] = commit;
        out[QELEMS + 1] = loss;
        out[QELEMS + 2] = usage;
    }
}

// ---------------------------------------------------------------------------
extern "C" void kernel_launch(void* const* d_in, const int* in_sizes, int n_in,
                              void* d_out, int out_size) {
    const float* z    = (const float*)d_in[0];
    const int*   used = (const int*)d_in[2];
    float*       out  = (float*)d_out;

    k_init<<<64, 256>>>(used);
    k_token<<<N_TOK, 128>>>(z, out);
    k_finish<<<1, 1024>>>(out);
}